// round 7
// baseline (speedup 1.0000x reference)
#include <cuda_runtime.h>
#include <math.h>

#define BB 4
#define NN 2048
#define CC 32
#define CONV 332.07156f
#define EPS 1e-6f

// ---- precompute geometry ----
#define PRE_THREADS 256
#define PRE_BLOCKS (BB * NN / PRE_THREADS)   // 32 (8 per batch)

// ---- pair geometry ----
#define PTHREADS 256
#define PIB 4                      // i-atoms per thread (2 packed pairs)
#define PANELS (BB * 2)            // 8 panels x 1024 i-rows
#define SPLITS 74                  // j-splits per panel
#define PBLOCKS (PANELS * SPLITS)  // 592 = 4 CTAs/SM x 8 warps

typedef unsigned long long u64;

// Scratch (no cudaMalloc allowed)
__device__ float4 g_S[BB * NN];            // {-x, -y, -z, w=s_i+s_j}  (i-side)
__device__ ulonglong2 g_Jxy[BB * NN];      // {{-x,-x},{-y,-y}} pre-duplicated
__device__ u64        g_Jz [BB * NN];      // {-z,-z}
__device__ double g_part_pair[PBLOCKS];
__device__ double g_part_self[PRE_BLOCKS]; // self + 0.5*diag-correction
__device__ unsigned int g_counter = 0;

// ---- packed f32x2 helpers (ptxas won't emit FFMA2 from C++) ----
__device__ __forceinline__ u64 pk2(float a, float b) {
    u64 r; asm("mov.b64 %0, {%1, %2};" : "=l"(r) : "f"(a), "f"(b)); return r;
}
__device__ __forceinline__ void upk2(float& a, float& b, u64 v) {
    asm("mov.b64 {%0, %1}, %2;" : "=f"(a), "=f"(b) : "l"(v));
}
__device__ __forceinline__ u64 add2(u64 a, u64 b) {
    u64 r; asm("add.rn.f32x2 %0, %1, %2;" : "=l"(r) : "l"(a), "l"(b)); return r;
}
__device__ __forceinline__ u64 fma2(u64 a, u64 b, u64 c) {
    u64 r; asm("fma.rn.f32x2 %0, %1, %2, %3;" : "=l"(r) : "l"(a), "l"(b), "l"(c)); return r;
}

// ============ kernel 1: per-atom precompute + self/diag partials ============
__global__ void __launch_bounds__(PRE_THREADS)
precompute_kernel(const float* __restrict__ X,
                  const float* __restrict__ embs,
                  const float* __restrict__ qs,
                  const float* __restrict__ born,
                  const float* __restrict__ die,
                  const float* __restrict__ filt)
{
    __shared__ double red[PRE_THREADS / 32];
    const int tid = threadIdx.x;
    const int idx = blockIdx.x * PRE_THREADS + tid;
    const float wd = filt[2 * CC];

    const float4* e4 = (const float4*)(embs + (long)idx * CC);
    const float4* fi = (const float4*)(filt);
    const float4* fj = (const float4*)(filt + CC);
    const float4* d4 = (const float4*)(die);
    const float4* b4 = (const float4*)(born);

    float si = 0.f, sj = 0.f, ad = EPS, R = 1.0f;
#pragma unroll
    for (int c = 0; c < CC / 4; c++) {
        float4 e = e4[c];
        float4 a = fi[c], bq = fj[c], d = d4[c], bo = b4[c];
        si = fmaf(e.x, a.x,  fmaf(e.y, a.y,  fmaf(e.z, a.z,  fmaf(e.w, a.w,  si))));
        sj = fmaf(e.x, bq.x, fmaf(e.y, bq.y, fmaf(e.z, bq.z, fmaf(e.w, bq.w, sj))));
        ad = fmaf(e.x, d.x,  fmaf(e.y, d.y,  fmaf(e.z, d.z,  fmaf(e.w, d.w,  ad))));
        R  = fmaf(e.x, bo.x, fmaf(e.y, bo.y, fmaf(e.z, bo.z, fmaf(e.w, bo.w, R))));
    }
    float es = -(1.0f - 1.0f / ad) * qs[idx] / (R + EPS);

    float nx = -X[idx * 3 + 0], ny = -X[idx * 3 + 1], nz = -X[idx * 3 + 2];
    g_S[idx]   = make_float4(nx, ny, nz, si + sj);
    g_Jxy[idx] = make_ulonglong2(pk2(nx, nx), pk2(ny, ny));
    g_Jz[idx]  = pk2(nz, nz);

    // exact diagonal correction: the pair loop credits (si+sj)*r0_hw + wd
    // for the j==i pair; the true value is (si+sj+wd*D0)/(D0+eps).
    double part;
    {
        float d2c = 3e-6f;
        asm volatile("" : "+f"(d2c));        // block constant folding
        float r0_hw = rsqrtf(d2c);           // identical MUFU value as pair loop
        double D0 = (double)sqrtf(d2c);
        double w  = (double)si + (double)sj;
        double exact = (w + (double)wd * D0) / (D0 + (double)EPS);
        double loopv = w * (double)r0_hw + (double)wd;
        double corr = exact - loopv;          // pair-sum channel (coeff 0.5)
        part = (double)es + 0.5 * corr;
    }
#pragma unroll
    for (int off = 16; off > 0; off >>= 1)
        part += __shfl_down_sync(0xffffffffu, part, off);
    if ((tid & 31) == 0) red[tid >> 5] = part;
    __syncthreads();
    if (tid == 0) {
        double s = 0.0;
#pragma unroll
        for (int w = 0; w < PRE_THREADS / 32; w++) s += red[w];
        g_part_self[blockIdx.x] = s;
    }
}

// ============ kernel 2: pairwise rowsums + finalize ============
// E_pair(batch) ~= sum_i w_i * sum_j r_ij + wd*N^2  (+exact diag corr from k1)
__global__ void __launch_bounds__(PTHREADS, 4)
pair_kernel(const float* __restrict__ filt, float* __restrict__ out)
{
    __shared__ double red[PTHREADS / 32];
    __shared__ bool isLast;

    const int tid = threadIdx.x;
    const int blk = blockIdx.x;
    const int p   = blk / SPLITS;           // panel 0..7
    const int jj  = blk % SPLITS;
    const int b   = p >> 1;
    const int itile = p & 1;
    const int j0 = b * NN + (jj * NN) / SPLITS;
    const int j1 = b * NN + ((jj + 1) * NN) / SPLITS;

    const float4* __restrict__ S = g_S + b * NN;
    const int ibase = itile * (PTHREADS * PIB) + tid;

    // packed i coordinates (stored negated; un-negate by negating again)
    u64 xi2[PIB / 2], yi2[PIB / 2], zi2[PIB / 2], acc2[PIB / 2];
#pragma unroll
    for (int kk = 0; kk < PIB / 2; kk++) {
        float4 a = __ldg(&S[ibase + (2 * kk)     * PTHREADS]);
        float4 c = __ldg(&S[ibase + (2 * kk + 1) * PTHREADS]);
        xi2[kk] = pk2(-a.x, -c.x);
        yi2[kk] = pk2(-a.y, -c.y);
        zi2[kk] = pk2(-a.z, -c.z);
        acc2[kk] = 0ull;
    }
    const u64 c3e6 = pk2(3e-6f, 3e-6f);

#pragma unroll 4
    for (int j = j0; j < j1; j++) {
        // pre-duplicated, pre-negated broadcast: zero packing movs
        ulonglong2 jxy = __ldg(&g_Jxy[j]);
        u64 nz2 = __ldg(&g_Jz[j]);
#pragma unroll
        for (int kk = 0; kk < PIB / 2; kk++) {
            u64 dx2 = add2(xi2[kk], jxy.x);
            u64 dy2 = add2(yi2[kk], jxy.y);
            u64 dz2 = add2(zi2[kk], nz2);
            u64 d2p = fma2(dz2, dz2, c3e6);
            d2p = fma2(dy2, dy2, d2p);
            d2p = fma2(dx2, dx2, d2p);
            float d2lo, d2hi;
            upk2(d2lo, d2hi, d2p);
            float rlo = rsqrtf(d2lo);
            float rhi = rsqrtf(d2hi);
            acc2[kk] = add2(acc2[kk], pk2(rlo, rhi));
        }
    }

    // weight by w_i (= s_i + s_j_i), combine in double
    double part = 0.0;
#pragma unroll
    for (int kk = 0; kk < PIB / 2; kk++) {
        float alo, ahi;
        upk2(alo, ahi, acc2[kk]);
        float wlo = __ldg(&S[ibase + (2 * kk)     * PTHREADS]).w;
        float whi = __ldg(&S[ibase + (2 * kk + 1) * PTHREADS]).w;
        part += (double)wlo * (double)alo + (double)whi * (double)ahi;
    }
#pragma unroll
    for (int off = 16; off > 0; off >>= 1)
        part += __shfl_down_sync(0xffffffffu, part, off);
    if ((tid & 31) == 0) red[tid >> 5] = part;
    __syncthreads();
    if (tid == 0) {
        double s = 0.0;
#pragma unroll
        for (int w = 0; w < PTHREADS / 32; w++) s += red[w];
        g_part_pair[blk] = s;
        __threadfence();
        unsigned int t = atomicAdd(&g_counter, 1u);
        isLast = (t == (unsigned)(gridDim.x - 1));
    }
    __syncthreads();
    if (!isLast) return;

    // ---- finalize: warp w (w<BB) handles batch w ----
    const int w = tid >> 5, lane = tid & 31;
    const float wd = filt[2 * CC];
    const int per_b = 2 * SPLITS;            // 148 pair partials per batch

    if (w < BB) {
        double pp = 0.0;
#pragma unroll
        for (int t = 0; t < 5; t++) {
            int idx = lane + t * 32;
            if (idx < per_b) pp += __ldcg(&g_part_pair[w * per_b + idx]);
        }
        double ss = (lane < PRE_BLOCKS / BB)
                  ? __ldcg(&g_part_self[w * (PRE_BLOCKS / BB) + lane]) : 0.0;
#pragma unroll
        for (int off = 16; off > 0; off >>= 1) {
            pp += __shfl_down_sync(0xffffffffu, pp, off);
            ss += __shfl_down_sync(0xffffffffu, ss, off);
        }
        if (lane == 0) {
            double pair = pp + (double)wd * (double)NN * (double)NN;
            float v = (float)((double)CONV * (ss + 0.5 * pair) * 0.01);
            if (isnan(v)) v = 1e-6f;
            out[w] = v;
        }
    }
    if (tid == 0) g_counter = 0;   // reset for next graph replay
}

extern "C" void kernel_launch(void* const* d_in, const int* in_sizes, int n_in,
                              void* d_out, int out_size) {
    const float* X    = (const float*)d_in[0];  // (B,N,3)
    const float* embs = (const float*)d_in[1];  // (B,N,C)
    const float* qs   = (const float*)d_in[2];  // (B,N)
    // d_in[3] = paired_mask (unused by reference)
    const float* born = (const float*)d_in[4];  // (C,)
    const float* die  = (const float*)d_in[5];  // (C,)
    const float* filt = (const float*)d_in[6];  // (2C+1, 1)
    float* out = (float*)d_out;

    precompute_kernel<<<PRE_BLOCKS, PRE_THREADS>>>(X, embs, qs, born, die, filt);
    pair_kernel<<<PBLOCKS, PTHREADS>>>(filt, out);
}

// round 8
// speedup vs baseline: 1.1082x; 1.1082x over previous
#include <cuda_runtime.h>
#include <math.h>

#define BB 4
#define NN 2048
#define CC 32
#define CONV 332.07156f
#define EPS 1e-6f

// ---- precompute geometry ----
#define PRE_THREADS 256
#define PRE_BLOCKS (BB * NN / PRE_THREADS)   // 32 (8 per batch)

// ---- pair geometry (symmetric panels) ----
#define PTHREADS 256
#define PIB 2                       // i-atoms per thread -> panel = 512 rows
#define PANEL 512
#define BLKS_PER_B 148              // 59+44+30+15 j-splits over panels 0..3
#define PBLOCKS (BB * BLKS_PER_B)   // 592 = 4 CTAs/SM on 148 SMs

// Scratch (no cudaMalloc allowed)
__device__ float4 g_S[BB * NN];            // {-x, -y, -z, w=s_i+s_j}
__device__ double g_part_pair[PBLOCKS];
__device__ double g_part_self[PRE_BLOCKS]; // self + 0.5*diag-correction
__device__ unsigned int g_counter = 0;

// ============ kernel 1: per-atom precompute + self/diag partials ============
__global__ void __launch_bounds__(PRE_THREADS)
precompute_kernel(const float* __restrict__ X,
                  const float* __restrict__ embs,
                  const float* __restrict__ qs,
                  const float* __restrict__ born,
                  const float* __restrict__ die,
                  const float* __restrict__ filt)
{
    __shared__ double red[PRE_THREADS / 32];
    const int tid = threadIdx.x;
    const int idx = blockIdx.x * PRE_THREADS + tid;
    const float wd = filt[2 * CC];

    const float4* e4 = (const float4*)(embs + (long)idx * CC);
    const float4* fi = (const float4*)(filt);
    const float4* fj = (const float4*)(filt + CC);
    const float4* d4 = (const float4*)(die);
    const float4* b4 = (const float4*)(born);

    float si = 0.f, sj = 0.f, ad = EPS, R = 1.0f;
#pragma unroll
    for (int c = 0; c < CC / 4; c++) {
        float4 e = e4[c];
        float4 a = fi[c], bq = fj[c], d = d4[c], bo = b4[c];
        si = fmaf(e.x, a.x,  fmaf(e.y, a.y,  fmaf(e.z, a.z,  fmaf(e.w, a.w,  si))));
        sj = fmaf(e.x, bq.x, fmaf(e.y, bq.y, fmaf(e.z, bq.z, fmaf(e.w, bq.w, sj))));
        ad = fmaf(e.x, d.x,  fmaf(e.y, d.y,  fmaf(e.z, d.z,  fmaf(e.w, d.w,  ad))));
        R  = fmaf(e.x, bo.x, fmaf(e.y, bo.y, fmaf(e.z, bo.z, fmaf(e.w, bo.w, R))));
    }
    float es = -(1.0f - 1.0f / ad) * qs[idx] / (R + EPS);

    g_S[idx] = make_float4(-X[idx * 3 + 0], -X[idx * 3 + 1], -X[idx * 3 + 2],
                           si + sj);

    // exact diagonal correction: the pair loop credits (si+sj)*r0_hw + wd
    // for the j==i pair; the true value is (si+sj+wd*D0)/(D0+eps).
    double part;
    {
        float d2c = 3e-6f;
        asm volatile("" : "+f"(d2c));        // block constant folding
        float r0_hw = rsqrtf(d2c);           // identical MUFU value as pair loop
        double D0 = (double)sqrtf(d2c);
        double w  = (double)si + (double)sj;
        double exact = (w + (double)wd * D0) / (D0 + (double)EPS);
        double loopv = w * (double)r0_hw + (double)wd;
        double corr = exact - loopv;          // pair-sum channel (coeff 0.5)
        part = (double)es + 0.5 * corr;
    }
#pragma unroll
    for (int off = 16; off > 0; off >>= 1)
        part += __shfl_down_sync(0xffffffffu, part, off);
    if ((tid & 31) == 0) red[tid >> 5] = part;
    __syncthreads();
    if (tid == 0) {
        double s = 0.0;
#pragma unroll
        for (int w = 0; w < PRE_THREADS / 32; w++) s += red[w];
        g_part_self[blockIdx.x] = s;
    }
}

// ============ kernel 2: symmetric pairwise + finalize ============
// Full matrix T = sum_ij w_i r_ij decomposed per 512-row panel p:
//   intra-panel [lo, lo+512):        sum w_i r_ij (full sub-matrix)
//   cross-panel [lo+512, 2048) once: sum (w_i + w_j) r_ij
// E_pair(batch) = T + wd*N^2 (+exact diag corr from k1)
__global__ void __launch_bounds__(PTHREADS, 4)
pair_kernel(const float* __restrict__ filt, float* __restrict__ out)
{
    __shared__ double red[PTHREADS / 32];
    __shared__ bool isLast;

    const int tid = threadIdx.x;
    const int blk = blockIdx.x;
    const int b   = blk / BLKS_PER_B;
    const int r   = blk % BLKS_PER_B;

    // panel + split within panel (splits: 59, 44, 30, 15)
    int p, rl, ns;
    if      (r <  59) { p = 0; rl = r;       ns = 59; }
    else if (r < 103) { p = 1; rl = r -  59; ns = 44; }
    else if (r < 133) { p = 2; rl = r - 103; ns = 30; }
    else              { p = 3; rl = r - 133; ns = 15; }

    const int lo  = PANEL * p;
    const int len = NN - lo;
    const int j0  = lo + (rl * len) / ns;
    const int j1  = lo + ((rl + 1) * len) / ns;
    const int selfEnd = lo + PANEL;

    const float4* __restrict__ S = g_S + b * NN;

    // this thread's PIB i-atoms within the panel
    float xi[PIB], yi[PIB], zi[PIB], wi[PIB], acc[PIB];
#pragma unroll
    for (int k = 0; k < PIB; k++) {
        float4 a = __ldg(&S[lo + k * PTHREADS + tid]);
        xi[k] = -a.x; yi[k] = -a.y; zi[k] = -a.z; wi[k] = a.w;
        acc[k] = 0.f;
    }
    float accw = 0.f;

    // ---- loop A: intra-panel region (full matrix, w_i weight) ----
    const int jA1 = (j1 < selfEnd) ? j1 : selfEnd;
#pragma unroll 4
    for (int j = j0; j < jA1; j++) {
        float4 pj = __ldg(&S[j]);          // negated coords, warp-uniform
#pragma unroll
        for (int k = 0; k < PIB; k++) {
            float dx = xi[k] + pj.x;
            float dy = yi[k] + pj.y;
            float dz = zi[k] + pj.z;
            float d2 = fmaf(dx, dx, fmaf(dy, dy, fmaf(dz, dz, 3e-6f)));
            acc[k] += rsqrtf(d2);
        }
    }

    // ---- loop B: cross-panel region (counted once, (w_i + w_j) weight) ----
    const int jB0 = (j0 > selfEnd) ? j0 : selfEnd;
#pragma unroll 4
    for (int j = jB0; j < j1; j++) {
        float4 pj = __ldg(&S[j]);
#pragma unroll
        for (int k = 0; k < PIB; k++) {
            float dx = xi[k] + pj.x;
            float dy = yi[k] + pj.y;
            float dz = zi[k] + pj.z;
            float d2 = fmaf(dx, dx, fmaf(dy, dy, fmaf(dz, dz, 3e-6f)));
            float rr = rsqrtf(d2);
            acc[k] += rr;
            accw = fmaf(pj.w, rr, accw);   // w_j side of symmetric pair
        }
    }

    // combine in double
    double part = (double)accw;
#pragma unroll
    for (int k = 0; k < PIB; k++)
        part += (double)wi[k] * (double)acc[k];
#pragma unroll
    for (int off = 16; off > 0; off >>= 1)
        part += __shfl_down_sync(0xffffffffu, part, off);
    if ((tid & 31) == 0) red[tid >> 5] = part;
    __syncthreads();
    if (tid == 0) {
        double s = 0.0;
#pragma unroll
        for (int w = 0; w < PTHREADS / 32; w++) s += red[w];
        g_part_pair[blk] = s;
        __threadfence();
        unsigned int t = atomicAdd(&g_counter, 1u);
        isLast = (t == (unsigned)(gridDim.x - 1));
    }
    __syncthreads();
    if (!isLast) return;

    // ---- finalize: warp w (w<BB) handles batch w ----
    const int w = tid >> 5, lane = tid & 31;
    const float wd = filt[2 * CC];

    if (w < BB) {
        double pp = 0.0;
#pragma unroll
        for (int t = 0; t < 5; t++) {
            int idx = lane + t * 32;
            if (idx < BLKS_PER_B) pp += __ldcg(&g_part_pair[w * BLKS_PER_B + idx]);
        }
        double ss = (lane < PRE_BLOCKS / BB)
                  ? __ldcg(&g_part_self[w * (PRE_BLOCKS / BB) + lane]) : 0.0;
#pragma unroll
        for (int off = 16; off > 0; off >>= 1) {
            pp += __shfl_down_sync(0xffffffffu, pp, off);
            ss += __shfl_down_sync(0xffffffffu, ss, off);
        }
        if (lane == 0) {
            double pair = pp + (double)wd * (double)NN * (double)NN;
            float v = (float)((double)CONV * (ss + 0.5 * pair) * 0.01);
            if (isnan(v)) v = 1e-6f;
            out[w] = v;
        }
    }
    if (tid == 0) g_counter = 0;   // reset for next graph replay
}

extern "C" void kernel_launch(void* const* d_in, const int* in_sizes, int n_in,
                              void* d_out, int out_size) {
    const float* X    = (const float*)d_in[0];  // (B,N,3)
    const float* embs = (const float*)d_in[1];  // (B,N,C)
    const float* qs   = (const float*)d_in[2];  // (B,N)
    // d_in[3] = paired_mask (unused by reference)
    const float* born = (const float*)d_in[4];  // (C,)
    const float* die  = (const float*)d_in[5];  // (C,)
    const float* filt = (const float*)d_in[6];  // (2C+1, 1)
    float* out = (float*)d_out;

    precompute_kernel<<<PRE_BLOCKS, PRE_THREADS>>>(X, embs, qs, born, die, filt);
    pair_kernel<<<PBLOCKS, PTHREADS>>>(filt, out);
}